// round 13
// baseline (speedup 1.0000x reference)
#include <cuda_runtime.h>

#define NTHREADS 512
#define GRID_BLOCKS (148 * 8)

// Zero-initialized accumulators; the last block resets them after reading,
// so every graph replay starts from zero.
__device__ double g_iou_sum;
__device__ double g_valid_cnt;
// Completion counter; atomicInc wraps to 0 at gridDim -> self-resetting.
__device__ unsigned int g_count;

// 256-bit read-only global load (sm_103a): two adjacent float4 boxes per LDG.
__device__ __forceinline__ void ldg_nc_v8(const float4* p, float4& a, float4& b) {
    asm("ld.global.nc.v8.f32 {%0, %1, %2, %3, %4, %5, %6, %7}, [%8];"
        : "=f"(a.x), "=f"(a.y), "=f"(a.z), "=f"(a.w),
          "=f"(b.x), "=f"(b.y), "=f"(b.z), "=f"(b.w)
        : "l"(p));
}

// Numerator (masked intersection) and denominator of one box IoU — no division.
__device__ __forceinline__ void iou_terms(const float4 p, const float4 t,
                                          float& num, float& den, float& cnt) {
    float phw = p.z * 0.5f, phh = p.w * 0.5f;
    float thw = t.z * 0.5f, thh = t.w * 0.5f;

    float ix = fminf(p.x + phw, t.x + thw) - fmaxf(p.x - phw, t.x - thw);
    float iy = fminf(p.y + phh, t.y + thh) - fmaxf(p.y - phh, t.y - thh);
    float inter = fmaxf(ix, 0.0f) * fmaxf(iy, 0.0f);

    float area_p = p.z * p.w;          // valid boxes have w,h >= 0
    float area_t = t.z * t.w;

    den = area_p + area_t - inter + 1e-6f;   // >= 1e-6 always
    bool valid = !(t.z == -1.0f && t.w == -1.0f);  // sentinel [-1]*4
    num = valid ? inter : 0.0f;
    cnt = valid ? 1.0f : 0.0f;
}

__global__ void __launch_bounds__(NTHREADS)
iou_reduce_kernel(const float4* __restrict__ pred,
                  const float4* __restrict__ truth,
                  int n, float* __restrict__ out, int out_size) {
    float lsum = 0.0f;
    float lcnt = 0.0f;

    int idx = blockIdx.x * NTHREADS + threadIdx.x;
    int stride = gridDim.x * NTHREADS;

    int npairs = n >> 1;
    // Natural grid-stride loop over box pairs; ONE division per pair:
    //   a0/d0 + a1/d1 = (a0*d1 + a1*d0) / (d0*d1)
    // halves MUFU.RCP pressure (the hidden co-limiter at R12).
    for (int i = idx; i < npairs; i += stride) {
        float4 p0, p1, t0, t1;
        ldg_nc_v8(pred + 2 * i, p0, p1);
        ldg_nc_v8(truth + 2 * i, t0, t1);

        float a0, d0, c0, a1, d1, c1;
        iou_terms(p0, t0, a0, d0, c0);
        iou_terms(p1, t1, a1, d1, c1);

        lsum += (a0 * d1 + a1 * d0) / (d0 * d1);
        lcnt += c0 + c1;
    }
    if ((n & 1) && idx == 0) {         // generality guard; n is even here
        float4 p = __ldg(pred + (n - 1));
        float4 t = __ldg(truth + (n - 1));
        float a, d, c;
        iou_terms(p, t, a, d, c);
        lsum += a / d;
        lcnt += c;
    }

    // Warp reduce
    #pragma unroll
    for (int off = 16; off > 0; off >>= 1) {
        lsum += __shfl_down_sync(0xffffffffu, lsum, off);
        lcnt += __shfl_down_sync(0xffffffffu, lcnt, off);
    }

    __shared__ float ssum[NTHREADS / 32];
    __shared__ float scnt[NTHREADS / 32];
    int warp = threadIdx.x >> 5;
    int lane = threadIdx.x & 31;
    if (lane == 0) {
        ssum[warp] = lsum;
        scnt[warp] = lcnt;
    }
    __syncthreads();

    __shared__ bool is_last;
    if (threadIdx.x == 0) {
        float bsum = 0.0f, bcnt = 0.0f;
        #pragma unroll
        for (int w = 0; w < NTHREADS / 32; w++) {
            bsum += ssum[w];
            bcnt += scnt[w];
        }
        atomicAdd(&g_iou_sum, (double)bsum);
        atomicAdd(&g_valid_cnt, (double)bcnt);
        __threadfence();
        unsigned int old = atomicInc(&g_count, gridDim.x - 1);
        is_last = (old == gridDim.x - 1);   // wraps to 0 -> self-resetting
    }
    __syncthreads();

    if (is_last && threadIdx.x == 0) {
        double s = g_iou_sum;
        double c = g_valid_cnt;
        float m = (c > 0.0) ? (float)(s / (c < 1.0 ? 1.0 : c)) : 0.0f;
        for (int i = 0; i < out_size; i++) out[i] = m;
        g_iou_sum = 0.0;        // deferred reset for the next replay
        g_valid_cnt = 0.0;
    }
}

extern "C" void kernel_launch(void* const* d_in, const int* in_sizes, int n_in,
                              void* d_out, int out_size) {
    const float4* pred  = (const float4*)d_in[0];
    const float4* truth = (const float4*)d_in[1];
    int n = in_sizes[0] / 4;   // number of boxes (float4 elements)

    int blocks = GRID_BLOCKS;
    int needed = (n / 2 + NTHREADS - 1) / NTHREADS;
    if (blocks > needed) blocks = needed;
    if (blocks < 1) blocks = 1;

    iou_reduce_kernel<<<blocks, NTHREADS>>>(pred, truth, n,
                                            (float*)d_out, out_size);
}

// round 14
// speedup vs baseline: 1.0018x; 1.0018x over previous
#include <cuda_runtime.h>

#define NTHREADS 512
#define NCTAS (148 * 4)
#define CHUNK_PAIRS 1024          // 2 pairs per thread per ticket

// Zero-initialized accumulators; last block resets them after reading.
__device__ double g_iou_sum;
__device__ double g_valid_cnt;
// Completion counter; atomicInc wraps to 0 at gridDim -> self-resetting.
__device__ unsigned int g_count;
// Work-stealing ticket counter. Starts at NCTAS (tickets 0..NCTAS-1 are taken
// statically by blockIdx). Final value each run = ntickets + NCTAS (each CTA
// consumes exactly one out-of-range ticket); last block resets it to NCTAS.
__device__ unsigned int g_ticket = NCTAS;

// 256-bit read-only global load (sm_103a): two adjacent float4 boxes per LDG.
__device__ __forceinline__ void ldg_nc_v8(const float4* p, float4& a, float4& b) {
    asm("ld.global.nc.v8.f32 {%0, %1, %2, %3, %4, %5, %6, %7}, [%8];"
        : "=f"(a.x), "=f"(a.y), "=f"(a.z), "=f"(a.w),
          "=f"(b.x), "=f"(b.y), "=f"(b.z), "=f"(b.w)
        : "l"(p));
}

__device__ __forceinline__ void iou_terms(const float4 p, const float4 t,
                                          float& num, float& den, float& cnt) {
    float phw = p.z * 0.5f, phh = p.w * 0.5f;
    float thw = t.z * 0.5f, thh = t.w * 0.5f;

    float ix = fminf(p.x + phw, t.x + thw) - fmaxf(p.x - phw, t.x - thw);
    float iy = fminf(p.y + phh, t.y + thh) - fmaxf(p.y - phh, t.y - thh);
    float inter = fmaxf(ix, 0.0f) * fmaxf(iy, 0.0f);

    float area_p = p.z * p.w;          // valid boxes have w,h >= 0
    float area_t = t.z * t.w;

    den = area_p + area_t - inter + 1e-6f;           // >= 1e-6 always
    bool valid = !(t.z == -1.0f && t.w == -1.0f);    // sentinel [-1]*4
    num = valid ? inter : 0.0f;
    cnt = valid ? 1.0f : 0.0f;
}

__device__ __forceinline__ void do_pair(const float4* __restrict__ pred,
                                        const float4* __restrict__ truth,
                                        int i, float& lsum, float& lcnt) {
    float4 p0, p1, t0, t1;
    ldg_nc_v8(pred + 2 * i, p0, p1);
    ldg_nc_v8(truth + 2 * i, t0, t1);
    float a0, d0, c0, a1, d1, c1;
    iou_terms(p0, t0, a0, d0, c0);
    iou_terms(p1, t1, a1, d1, c1);
    lsum += (a0 * d1 + a1 * d0) / (d0 * d1);   // one RCP per 2 boxes
    lcnt += c0 + c1;
}

__global__ void __launch_bounds__(NTHREADS)
iou_reduce_kernel(const float4* __restrict__ pred,
                  const float4* __restrict__ truth,
                  int n, int npairs, int ntickets,
                  float* __restrict__ out, int out_size) {
    __shared__ unsigned int sh_t[2];

    float lsum = 0.0f;
    float lcnt = 0.0f;
    const int tid = threadIdx.x;

    if (tid == 0) sh_t[0] = blockIdx.x;   // static first ticket
    __syncthreads();

    int cur = 0;
    while (true) {
        unsigned int t = sh_t[cur];
        if (t >= (unsigned int)ntickets) break;
        // Prefetch next ticket; atomic latency overlaps the chunk body.
        if (tid == 0) sh_t[cur ^ 1] = atomicAdd(&g_ticket, 1u);

        int base = (int)t * CHUNK_PAIRS;
        int i0 = base + tid;
        int i1 = base + tid + NTHREADS;
        if (i0 < npairs) do_pair(pred, truth, i0, lsum, lcnt);
        if (i1 < npairs) do_pair(pred, truth, i1, lsum, lcnt);

        cur ^= 1;
        __syncthreads();
    }

    // Odd-box guard (n is even for this problem).
    if ((n & 1) && blockIdx.x == 0 && tid == 0) {
        float4 p = __ldg(pred + (n - 1));
        float4 t = __ldg(truth + (n - 1));
        float a, d, c;
        iou_terms(p, t, a, d, c);
        lsum += a / d;
        lcnt += c;
    }

    // Warp reduce
    #pragma unroll
    for (int off = 16; off > 0; off >>= 1) {
        lsum += __shfl_down_sync(0xffffffffu, lsum, off);
        lcnt += __shfl_down_sync(0xffffffffu, lcnt, off);
    }

    __shared__ float ssum[NTHREADS / 32];
    __shared__ float scnt[NTHREADS / 32];
    int warp = tid >> 5;
    int lane = tid & 31;
    if (lane == 0) { ssum[warp] = lsum; scnt[warp] = lcnt; }
    __syncthreads();

    __shared__ bool is_last;
    if (tid == 0) {
        float bsum = 0.0f, bcnt = 0.0f;
        #pragma unroll
        for (int w = 0; w < NTHREADS / 32; w++) { bsum += ssum[w]; bcnt += scnt[w]; }
        atomicAdd(&g_iou_sum, (double)bsum);
        atomicAdd(&g_valid_cnt, (double)bcnt);
        __threadfence();
        unsigned int old = atomicInc(&g_count, gridDim.x - 1);
        is_last = (old == gridDim.x - 1);   // wraps to 0 -> self-resetting
    }
    __syncthreads();

    if (is_last && tid == 0) {
        double s = g_iou_sum;
        double c = g_valid_cnt;
        float m = (c > 0.0) ? (float)(s / (c < 1.0 ? 1.0 : c)) : 0.0f;
        for (int i = 0; i < out_size; i++) out[i] = m;
        g_iou_sum = 0.0;          // deferred resets for next replay
        g_valid_cnt = 0.0;
        g_ticket = NCTAS;
    }
}

extern "C" void kernel_launch(void* const* d_in, const int* in_sizes, int n_in,
                              void* d_out, int out_size) {
    const float4* pred  = (const float4*)d_in[0];
    const float4* truth = (const float4*)d_in[1];
    int n = in_sizes[0] / 4;        // number of boxes
    int npairs = n >> 1;
    int ntickets = (npairs + CHUNK_PAIRS - 1) / CHUNK_PAIRS;

    iou_reduce_kernel<<<NCTAS, NTHREADS>>>(pred, truth, n, npairs, ntickets,
                                           (float*)d_out, out_size);
}